// round 2
// baseline (speedup 1.0000x reference)
#include <cuda_runtime.h>

// Problem constants
// B=4, S=2048, PAST=2048, D_IN=2048, D_H=2048, D_FF=8192
// Output layout (flattened tree (out,(k,v))):
//   out  : [4,2048,2048]  = 16,777,216 floats
//   k    : [4,4096,2048]  = 33,554,432 floats
//   v    : [4,4096,2048]  = 33,554,432 floats

#define NB    4
#define SQ    2048
#define PAST  2048
#define DIN   2048
#define DH    2048
#define DFF   8192
#define KVLEN (PAST + SQ)   // 4096

// ---------------- scratch (device globals; no allocation allowed) -------------
__device__ float g_q[(long long)NB * SQ * DH];          // 64 MB
__device__ float g_scores[(long long)NB * SQ * KVLEN];  // 134 MB
__device__ float g_ctx[(long long)NB * SQ * DH];        // 64 MB
__device__ float g_ff[(long long)NB * SQ * DFF];        // 256 MB

// ---------------- SGEMM: C = A @ B (+bias), optional B transposed -------------
// A: [M,K] row-major (per batch, batch stride aBatch)
// B: if !TRANSB: [K,N] row-major;  if TRANSB: [N,K] row-major  (batch stride bBatch)
// C row (per batch z): global row = z*cBatchRows + cRowOff + m, ldc = N
// Tiling: 128x128x8, 256 threads, 8x8 per thread (split 4+4 fragments).
template<bool TRANSB>
__global__ __launch_bounds__(256, 2)
void sgemm(const float* __restrict__ A, const float* __restrict__ B,
           const float* __restrict__ bias, float* __restrict__ C,
           int M, int N, int K,
           long long aBatch, long long bBatch,
           int cBatchRows, int cRowOff)
{
    __shared__ __align__(16) float As[2][8][132];
    __shared__ __align__(16) float Bs[2][8][132];

    const int tid = threadIdx.x;
    const int tx  = tid & 15;
    const int ty  = tid >> 4;
    const int bn0 = blockIdx.x * 128;
    const int bm0 = blockIdx.y * 128;

    A += (long long)blockIdx.z * aBatch;
    B += (long long)blockIdx.z * bBatch;

    // A tile loader: one float4 per thread. row 0..127, k-offset 0 or 4.
    const int arow = tid >> 1;
    const int akc  = (tid & 1) << 2;
    const float* aptr = A + (long long)(bm0 + arow) * K + akc;

    // B tile loader
    int b_r0, b_c0;
    const float* bptr;
    if (TRANSB) {
        b_r0 = tid >> 1;            // n within tile (0..127)
        b_c0 = (tid & 1) << 2;      // k within tile (0 or 4)
        bptr = B + (long long)(bn0 + b_r0) * K + b_c0;
    } else {
        b_r0 = tid >> 5;            // k within tile (0..7)
        b_c0 = (tid & 31) << 2;     // n within tile (0..124)
        bptr = B + (long long)b_r0 * N + bn0 + b_c0;
    }

    float4 aReg = *(const float4*)aptr;
    float4 bReg = *(const float4*)bptr;

    As[0][akc + 0][arow] = aReg.x;
    As[0][akc + 1][arow] = aReg.y;
    As[0][akc + 2][arow] = aReg.z;
    As[0][akc + 3][arow] = aReg.w;
    if (TRANSB) {
        Bs[0][b_c0 + 0][b_r0] = bReg.x;
        Bs[0][b_c0 + 1][b_r0] = bReg.y;
        Bs[0][b_c0 + 2][b_r0] = bReg.z;
        Bs[0][b_c0 + 3][b_r0] = bReg.w;
    } else {
        *(float4*)&Bs[0][b_r0][b_c0] = bReg;
    }
    __syncthreads();

    float acc[8][8];
#pragma unroll
    for (int i = 0; i < 8; i++)
#pragma unroll
        for (int j = 0; j < 8; j++) acc[i][j] = 0.f;

    const int nT = K >> 3;
    int buf = 0;
    for (int t = 0; t < nT; t++) {
        if (t + 1 < nT) {
            aReg = *(const float4*)(aptr + ((t + 1) << 3));
            if (TRANSB) bReg = *(const float4*)(bptr + ((t + 1) << 3));
            else        bReg = *(const float4*)(bptr + (long long)((t + 1) << 3) * N);
        }
#pragma unroll
        for (int kk = 0; kk < 8; kk++) {
            const float4 a0 = *(const float4*)&As[buf][kk][ty << 2];
            const float4 a1 = *(const float4*)&As[buf][kk][64 + (ty << 2)];
            const float4 b0 = *(const float4*)&Bs[buf][kk][tx << 2];
            const float4 b1 = *(const float4*)&Bs[buf][kk][64 + (tx << 2)];
            const float a[8] = {a0.x, a0.y, a0.z, a0.w, a1.x, a1.y, a1.z, a1.w};
            const float b[8] = {b0.x, b0.y, b0.z, b0.w, b1.x, b1.y, b1.z, b1.w};
#pragma unroll
            for (int i = 0; i < 8; i++)
#pragma unroll
                for (int j = 0; j < 8; j++)
                    acc[i][j] = fmaf(a[i], b[j], acc[i][j]);
        }
        if (t + 1 < nT) {
            buf ^= 1;
            As[buf][akc + 0][arow] = aReg.x;
            As[buf][akc + 1][arow] = aReg.y;
            As[buf][akc + 2][arow] = aReg.z;
            As[buf][akc + 3][arow] = aReg.w;
            if (TRANSB) {
                Bs[buf][b_c0 + 0][b_r0] = bReg.x;
                Bs[buf][b_c0 + 1][b_r0] = bReg.y;
                Bs[buf][b_c0 + 2][b_r0] = bReg.z;
                Bs[buf][b_c0 + 3][b_r0] = bReg.w;
            } else {
                *(float4*)&Bs[buf][b_r0][b_c0] = bReg;
            }
            __syncthreads();
        }
    }

    // epilogue
    float4 bias0 = make_float4(0.f, 0.f, 0.f, 0.f);
    float4 bias1 = bias0;
    if (bias) {
        bias0 = *(const float4*)&bias[bn0 + (tx << 2)];
        bias1 = *(const float4*)&bias[bn0 + 64 + (tx << 2)];
    }
    const long long rowBase = (long long)blockIdx.z * cBatchRows + cRowOff + bm0;
#pragma unroll
    for (int i = 0; i < 8; i++) {
        const int r = (i < 4) ? ((ty << 2) + i) : (64 + (ty << 2) + (i - 4));
        float* crow = C + (rowBase + r) * (long long)N + bn0;
        float4 v0, v1;
        v0.x = acc[i][0] + bias0.x;  v0.y = acc[i][1] + bias0.y;
        v0.z = acc[i][2] + bias0.z;  v0.w = acc[i][3] + bias0.w;
        v1.x = acc[i][4] + bias1.x;  v1.y = acc[i][5] + bias1.y;
        v1.z = acc[i][6] + bias1.z;  v1.w = acc[i][7] + bias1.w;
        *(float4*)&crow[tx << 2]      = v0;
        *(float4*)&crow[64 + (tx << 2)] = v1;
    }
}

// --------- copy past KV caches into the output cache region -------------------
// k_cache/v_cache: [4,2048,2048] -> dst rows b*4096 + r (first PAST rows)
__global__ void cache_copy(const float* __restrict__ kc, const float* __restrict__ vc,
                           float* __restrict__ kout, float* __restrict__ vout)
{
    const long long per = (long long)PAST * DH / 4;     // float4 per batch
    const long long tot = per * NB;
    for (long long i = (long long)blockIdx.x * blockDim.x + threadIdx.x;
         i < tot; i += (long long)gridDim.x * blockDim.x) {
        const int b = (int)(i / per);
        const long long o = i - (long long)b * per;
        const long long dst = (long long)b * (KVLEN * (long long)DH / 4) + o;
        ((float4*)kout)[dst] = ((const float4*)kc)[i];
        ((float4*)vout)[dst] = ((const float4*)vc)[i];
    }
}

// --------- softmax over the QUERY axis (dim 1 of [B, SQ, KVLEN]) --------------
// One thread per key-column; loop over 2048 query rows (coalesced across keys).
__global__ void softmax_qaxis(float* __restrict__ s)
{
    const int col = blockIdx.x * blockDim.x + threadIdx.x;   // 0..KVLEN-1
    const int b   = blockIdx.y;
    float* base = s + (long long)b * SQ * KVLEN + col;

    float mx = -1e30f;
    for (int r = 0; r < SQ; r++) mx = fmaxf(mx, base[(long long)r * KVLEN]);
    float sum = 0.f;
    for (int r = 0; r < SQ; r++) {
        const long long idx = (long long)r * KVLEN;
        const float e = __expf(base[idx] - mx);
        base[idx] = e;
        sum += e;
    }
    const float inv = 1.f / sum;
    for (int r = 0; r < SQ; r++) {
        const long long idx = (long long)r * KVLEN;
        base[idx] *= inv;
    }
}

// -----------------------------------------------------------------------------
extern "C" void kernel_launch(void* const* d_in, const int* in_sizes, int n_in,
                              void* d_out, int out_size)
{
    const float* x    = (const float*)d_in[0];
    const float* kc   = (const float*)d_in[1];
    const float* vc   = (const float*)d_in[2];
    const float* Wq   = (const float*)d_in[3];
    const float* bq   = (const float*)d_in[4];
    const float* Wk   = (const float*)d_in[5];
    const float* bk   = (const float*)d_in[6];
    const float* Wv   = (const float*)d_in[7];
    const float* bv   = (const float*)d_in[8];
    const float* Wff  = (const float*)d_in[9];
    const float* bff  = (const float*)d_in[10];
    const float* Wout = (const float*)d_in[11];
    const float* bout = (const float*)d_in[12];

    float* out  = (float*)d_out;
    float* kout = out  + (long long)NB * SQ * DH;      // [4,4096,2048]
    float* vout = kout + (long long)NB * KVLEN * DH;   // [4,4096,2048]

    void *qp, *sp, *cp, *fp;
    cudaGetSymbolAddress(&qp, g_q);
    cudaGetSymbolAddress(&sp, g_scores);
    cudaGetSymbolAddress(&cp, g_ctx);
    cudaGetSymbolAddress(&fp, g_ff);
    float* q      = (float*)qp;
    float* scores = (float*)sp;
    float* ctx    = (float*)cp;
    float* ff     = (float*)fp;

    // 1) copy past KV into output cache region
    cache_copy<<<2048, 256>>>(kc, vc, kout, vout);

    // 2) projections (batched over z=4, M=2048 per batch)
    {
        dim3 grid(DH / 128, SQ / 128, NB);
        sgemm<false><<<grid, 256>>>(x, Wq, bq, q,    SQ, DH, DIN,
                                    (long long)SQ * DIN, 0, SQ, 0);
        sgemm<false><<<grid, 256>>>(x, Wk, bk, kout, SQ, DH, DIN,
                                    (long long)SQ * DIN, 0, KVLEN, PAST);
        sgemm<false><<<grid, 256>>>(x, Wv, bv, vout, SQ, DH, DIN,
                                    (long long)SQ * DIN, 0, KVLEN, PAST);
    }

    // 3) scores[b] = q[b] @ k[b]^T   (NT: B is [KVLEN, DH] row-major)
    {
        dim3 grid(KVLEN / 128, SQ / 128, NB);
        sgemm<true><<<grid, 256>>>(q, kout, nullptr, scores, SQ, KVLEN, DH,
                                   (long long)SQ * DH, (long long)KVLEN * DH, SQ, 0);
    }

    // 4) softmax over query axis
    {
        dim3 grid(KVLEN / 256, NB);
        softmax_qaxis<<<grid, 256>>>(scores);
    }

    // 5) ctx[b] = attn[b] @ v[b]   (NN, K=KVLEN)
    {
        dim3 grid(DH / 128, SQ / 128, NB);
        sgemm<false><<<grid, 256>>>(scores, vout, nullptr, ctx, SQ, DH, KVLEN,
                                    (long long)SQ * KVLEN, (long long)KVLEN * DH, SQ, 0);
    }

    // 6) FFN: ff = ctx @ Wff + bff ; out = ff @ Wout + bout  (single big M)
    {
        const int M = NB * SQ;  // 8192
        dim3 g1(DFF / 128, M / 128, 1);
        sgemm<false><<<g1, 256>>>(ctx, Wff, bff, ff, M, DFF, DH, 0, 0, M, 0);
        dim3 g2(DH / 128, M / 128, 1);
        sgemm<false><<<g2, 256>>>(ff, Wout, bout, out, M, DH, DFF, 0, 0, M, 0);
    }
}

// round 5
// speedup vs baseline: 1.8235x; 1.8235x over previous
#include <cuda_runtime.h>
#include <cuda_bf16.h>
#include <cstdint>

#define NB    4
#define SQ    2048
#define PAST  2048
#define DIN   2048
#define DH    2048
#define DFF   8192
#define KVLEN (PAST + SQ)   // 4096

// ======================= device scratch (no allocation allowed) ==============
__device__ float g_scores[(long long)NB * SQ * KVLEN];   // 134 MB
// bf16 split operands (K' = 3K concatenation)
__device__ __nv_bfloat16 g_xs   [(long long)NB*SQ * 3*DIN];
__device__ __nv_bfloat16 g_qs   [(long long)NB*SQ * 3*DH];
__device__ __nv_bfloat16 g_ks   [(long long)NB*KVLEN * 3*DH];
__device__ __nv_bfloat16 g_vts  [(long long)NB*DH * 3*KVLEN];
__device__ __nv_bfloat16 g_attns[(long long)NB*SQ * 3*KVLEN];
__device__ __nv_bfloat16 g_ctxs [(long long)NB*SQ * 3*DH];
__device__ __nv_bfloat16 g_ffs  [(long long)NB*SQ * 3*DFF];
__device__ __nv_bfloat16 g_wqs  [(long long)DH * 3*DIN];
__device__ __nv_bfloat16 g_wks  [(long long)DH * 3*DIN];
__device__ __nv_bfloat16 g_wvs  [(long long)DH * 3*DIN];
__device__ __nv_bfloat16 g_wffs [(long long)DFF * 3*DH];
__device__ __nv_bfloat16 g_wouts[(long long)DH * 3*DFF];

// ======================= helpers =============================================
__device__ __forceinline__ uint32_t smem_u32(const void* p) {
    uint32_t a;
    asm("{ .reg .u64 t; cvta.to.shared.u64 t, %1; cvt.u32.u64 %0, t; }" : "=r"(a) : "l"(p));
    return a;
}
__device__ __forceinline__ void ldm4(uint32_t* f, uint32_t a) {
    asm volatile("ldmatrix.sync.aligned.m8n8.x4.shared.b16 {%0,%1,%2,%3}, [%4];"
                 : "=r"(f[0]), "=r"(f[1]), "=r"(f[2]), "=r"(f[3]) : "r"(a));
}
__device__ __forceinline__ void mma16816(float* c, const uint32_t* a, uint32_t b0, uint32_t b1) {
    asm volatile("mma.sync.aligned.m16n8k16.row.col.f32.bf16.bf16.f32 "
                 "{%0,%1,%2,%3}, {%4,%5,%6,%7}, {%8,%9}, {%0,%1,%2,%3};"
                 : "+f"(c[0]), "+f"(c[1]), "+f"(c[2]), "+f"(c[3])
                 : "r"(a[0]), "r"(a[1]), "r"(a[2]), "r"(a[3]), "r"(b0), "r"(b1));
}
__device__ __forceinline__ unsigned short bf16bits(float f) {
    __nv_bfloat16 h = __float2bfloat16(f);
    return *reinterpret_cast<unsigned short*>(&h);
}
__device__ __forceinline__ float bf16val(unsigned short u) {
    __nv_bfloat16 h = *reinterpret_cast<__nv_bfloat16*>(&u);
    return __bfloat162float(h);
}
// swizzled byte offset of 16B segment j (0..3) in 64B row r
__device__ __forceinline__ uint32_t swz(int r, int j) {
    return (uint32_t)(r * 64 + ((j ^ ((r >> 1) & 3)) << 4));
}

// ======================= GEMM: C[M,N] = A[M,K']·B[N,K']^T (bf16 HMMA) ========
// Tile 128x128x32, 8 warps (4M x 2N), each warp 32x64. Double-buffered SMEM.
// C may be null (split-only output). sA optional: bf16 split (hi,hi,lo), stride 3N.
__global__ void __launch_bounds__(256, 2)
gemm_mma(const __nv_bfloat16* __restrict__ A, const __nv_bfloat16* __restrict__ B,
         const float* __restrict__ bias, float* __restrict__ C,
         __nv_bfloat16* __restrict__ sA,
         int N, long long Kp,
         long long aBatch, long long bBatch,
         int cBatchRows, int cRowOff)
{
    __shared__ __align__(16) uint8_t As[2][8192];
    __shared__ __align__(16) uint8_t Bs[2][8192];

    const int tid = threadIdx.x;
    const int wid = tid >> 5;
    const int lid = tid & 31;
    const long long bn0 = (long long)blockIdx.x * 128;
    const long long bm0 = (long long)blockIdx.y * 128;

    A += (long long)blockIdx.z * aBatch + bm0 * Kp;
    B += (long long)blockIdx.z * bBatch + bn0 * Kp;

    // loader: each thread owns 2 segments per operand (512 segs = 128 rows x 4)
    const int u0 = tid, u1 = tid + 256;
    const int lr0 = u0 >> 2, lj0 = u0 & 3;
    const int lr1 = u1 >> 2, lj1 = u1 & 3;
    const __nv_bfloat16* aG0 = A + (long long)lr0 * Kp + lj0 * 8;
    const __nv_bfloat16* aG1 = A + (long long)lr1 * Kp + lj1 * 8;
    const __nv_bfloat16* bG0 = B + (long long)lr0 * Kp + lj0 * 8;
    const __nv_bfloat16* bG1 = B + (long long)lr1 * Kp + lj1 * 8;
    const uint32_t sa0 = swz(lr0, lj0), sa1 = swz(lr1, lj1);

    // prologue: chunk 0
    *(uint4*)(As[0] + sa0) = *(const uint4*)aG0;
    *(uint4*)(As[0] + sa1) = *(const uint4*)aG1;
    *(uint4*)(Bs[0] + sa0) = *(const uint4*)bG0;
    *(uint4*)(Bs[0] + sa1) = *(const uint4*)bG1;
    __syncthreads();

    // fragment addressing
    const int wm = wid >> 1, wn = wid & 1;
    const int l15 = lid & 15, h = lid >> 4;
    const uint32_t aSm = smem_u32(As), bSm = smem_u32(Bs);
    uint32_t aoff[2]; int ax[2];
#pragma unroll
    for (int i = 0; i < 2; i++) {
        const int r = wm * 32 + i * 16 + l15;
        aoff[i] = r * 64; ax[i] = (r >> 1) & 3;
    }
    uint32_t boff[4]; int bx[4];
#pragma unroll
    for (int g = 0; g < 4; g++) {
        const int r = wn * 64 + g * 16 + l15;
        boff[g] = r * 64; bx[g] = (r >> 1) & 3;
    }

    float acc[2][8][4];
#pragma unroll
    for (int i = 0; i < 2; i++)
#pragma unroll
        for (int j = 0; j < 8; j++)
#pragma unroll
            for (int k = 0; k < 4; k++) acc[i][j][k] = 0.f;

    const int nT = (int)(Kp >> 5);
    int buf = 0;
    for (int t = 0; t < nT; t++) {
        uint4 va0, va1, vb0, vb1;
        if (t + 1 < nT) {
            const long long o = (long long)(t + 1) * 32;
            va0 = *(const uint4*)(aG0 + o);
            va1 = *(const uint4*)(aG1 + o);
            vb0 = *(const uint4*)(bG0 + o);
            vb1 = *(const uint4*)(bG1 + o);
        }
        const uint32_t aB = aSm + buf * 8192;
        const uint32_t bB = bSm + buf * 8192;
#pragma unroll
        for (int s = 0; s < 2; s++) {
            uint32_t af[2][4], bfr[4][4];
            const int jb = 2 * s + h;
#pragma unroll
            for (int i = 0; i < 2; i++)
                ldm4(af[i], aB + aoff[i] + (uint32_t)(((jb ^ ax[i]) << 4)));
#pragma unroll
            for (int g = 0; g < 4; g++)
                ldm4(bfr[g], bB + boff[g] + (uint32_t)(((jb ^ bx[g]) << 4)));
#pragma unroll
            for (int mi = 0; mi < 2; mi++)
#pragma unroll
                for (int g = 0; g < 4; g++) {
                    mma16816(acc[mi][2 * g],     af[mi], bfr[g][0], bfr[g][2]);
                    mma16816(acc[mi][2 * g + 1], af[mi], bfr[g][1], bfr[g][3]);
                }
        }
        if (t + 1 < nT) {
            buf ^= 1;
            *(uint4*)(As[buf] + sa0) = va0;
            *(uint4*)(As[buf] + sa1) = va1;
            *(uint4*)(Bs[buf] + sa0) = vb0;
            *(uint4*)(Bs[buf] + sa1) = vb1;
            __syncthreads();
        }
    }

    // epilogue
    const long long rowBase = (long long)blockIdx.z * cBatchRows + cRowOff + bm0 + wm * 32;
    const int colW = (int)bn0 + wn * 64;
#pragma unroll
    for (int mi = 0; mi < 2; mi++) {
        const long long r0 = rowBase + mi * 16 + (lid >> 2);
        const long long r1 = r0 + 8;
#pragma unroll
        for (int nj = 0; nj < 8; nj++) {
            const int col = colW + nj * 8 + (lid & 3) * 2;
            float b0 = 0.f, b1 = 0.f;
            if (bias) { b0 = bias[col]; b1 = bias[col + 1]; }
            const float v00 = acc[mi][nj][0] + b0, v01 = acc[mi][nj][1] + b1;
            const float v10 = acc[mi][nj][2] + b0, v11 = acc[mi][nj][3] + b1;
            if (C) {
                *(float2*)&C[r0 * N + col] = make_float2(v00, v01);
                *(float2*)&C[r1 * N + col] = make_float2(v10, v11);
            }
            if (sA) {
                unsigned short h0 = bf16bits(v00), h1 = bf16bits(v01);
                ushort2 H = { h0, h1 };
                ushort2 L = { bf16bits(v00 - bf16val(h0)), bf16bits(v01 - bf16val(h1)) };
                unsigned short* sr = (unsigned short*)(sA + r0 * (3LL * N));
                *(ushort2*)(sr + col) = H;
                *(ushort2*)(sr + N + col) = H;
                *(ushort2*)(sr + 2LL * N + col) = L;
                h0 = bf16bits(v10); h1 = bf16bits(v11);
                H = { h0, h1 };
                L = { bf16bits(v10 - bf16val(h0)), bf16bits(v11 - bf16val(h1)) };
                sr = (unsigned short*)(sA + r1 * (3LL * N));
                *(ushort2*)(sr + col) = H;
                *(ushort2*)(sr + N + col) = H;
                *(ushort2*)(sr + 2LL * N + col) = L;
            }
        }
    }
}

// ======================= split / transpose kernels ===========================
// BSPLIT=false: segments (hi,hi,lo) [A operand]; true: (hi,lo,hi) [B operand]
template<bool BSPLIT>
__global__ void split_rows(const float* __restrict__ in, __nv_bfloat16* __restrict__ out,
                           long long R, int K)
{
    const long long total = R * (long long)(K >> 2);
    const int K4 = K >> 2;
    for (long long i = (long long)blockIdx.x * blockDim.x + threadIdx.x;
         i < total; i += (long long)gridDim.x * blockDim.x) {
        const long long r = i / K4;
        const int k = (int)(i - r * K4) << 2;
        const float4 v = ((const float4*)in)[i];
        ushort4 H, L;
        H.x = bf16bits(v.x); L.x = bf16bits(v.x - bf16val(H.x));
        H.y = bf16bits(v.y); L.y = bf16bits(v.y - bf16val(H.y));
        H.z = bf16bits(v.z); L.z = bf16bits(v.z - bf16val(H.z));
        H.w = bf16bits(v.w); L.w = bf16bits(v.w - bf16val(H.w));
        unsigned short* row = (unsigned short*)(out + r * (3LL * K));
        *(ushort4*)(row + k) = H;
        if (BSPLIT) { *(ushort4*)(row + K + k) = L; *(ushort4*)(row + 2 * K + k) = H; }
        else        { *(ushort4*)(row + K + k) = H; *(ushort4*)(row + 2 * K + k) = L; }
    }
}

// in fp32 [Kd, Nd] row-major -> out bf16 [Nd, 3*Kd], segments (hi,lo,hi)
__global__ void transpose_split(const float* __restrict__ in, __nv_bfloat16* __restrict__ out,
                                int Kd, int Nd, long long inBatch, long long outBatch)
{
    __shared__ float tile[32][33];
    in  += (long long)blockIdx.z * inBatch;
    out += (long long)blockIdx.z * outBatch;
    const int k0 = blockIdx.y * 32, n0 = blockIdx.x * 32;
    for (int i = threadIdx.y; i < 32; i += 8)
        tile[i][threadIdx.x] = in[(long long)(k0 + i) * Nd + n0 + threadIdx.x];
    __syncthreads();
    for (int i = threadIdx.y; i < 32; i += 8) {
        const int n = n0 + i, k = k0 + threadIdx.x;
        const float v = tile[threadIdx.x][i];
        const unsigned short hb = bf16bits(v);
        const unsigned short lb = bf16bits(v - bf16val(hb));
        unsigned short* row = (unsigned short*)(out + (long long)n * (3LL * Kd));
        row[k] = hb; row[Kd + k] = lb; row[2 * Kd + k] = hb;
    }
}

// ======================= softmax over QUERY axis + attn split ================
__global__ void softmax_split(float* __restrict__ s, __nv_bfloat16* __restrict__ attns)
{
    const int col = blockIdx.x * blockDim.x + threadIdx.x;
    const int b = blockIdx.y;
    float* base = s + (long long)b * SQ * KVLEN + col;
    float mx = -1e30f;
    for (int r = 0; r < SQ; r++) mx = fmaxf(mx, base[(long long)r * KVLEN]);
    float sum = 0.f;
    for (int r = 0; r < SQ; r++) {
        const long long idx = (long long)r * KVLEN;
        const float e = __expf(base[idx] - mx);
        base[idx] = e;
        sum += e;
    }
    const float inv = 1.f / sum;
    for (int r = 0; r < SQ; r++) {
        const float v = base[(long long)r * KVLEN] * inv;
        const unsigned short hb = bf16bits(v);
        const unsigned short lb = bf16bits(v - bf16val(hb));
        unsigned short* a = (unsigned short*)(attns + ((long long)b * SQ + r) * (3LL * KVLEN));
        a[col] = hb; a[KVLEN + col] = hb; a[2 * KVLEN + col] = lb;
    }
}

// ======================= KV cache copy =======================================
__global__ void cache_copy(const float* __restrict__ kc, const float* __restrict__ vc,
                           float* __restrict__ kout, float* __restrict__ vout)
{
    const long long per = (long long)PAST * DH / 4;
    const long long tot = per * NB;
    for (long long i = (long long)blockIdx.x * blockDim.x + threadIdx.x;
         i < tot; i += (long long)gridDim.x * blockDim.x) {
        const int b = (int)(i / per);
        const long long o = i - (long long)b * per;
        const long long dst = (long long)b * ((long long)KVLEN * DH / 4) + o;
        ((float4*)kout)[dst] = ((const float4*)kc)[i];
        ((float4*)vout)[dst] = ((const float4*)vc)[i];
    }
}

// =============================================================================
extern "C" void kernel_launch(void* const* d_in, const int* in_sizes, int n_in,
                              void* d_out, int out_size)
{
    const float* x    = (const float*)d_in[0];
    const float* kc   = (const float*)d_in[1];
    const float* vc   = (const float*)d_in[2];
    const float* Wq   = (const float*)d_in[3];
    const float* bq   = (const float*)d_in[4];
    const float* Wk   = (const float*)d_in[5];
    const float* bk   = (const float*)d_in[6];
    const float* Wv   = (const float*)d_in[7];
    const float* bv   = (const float*)d_in[8];
    const float* Wff  = (const float*)d_in[9];
    const float* bff  = (const float*)d_in[10];
    const float* Wout = (const float*)d_in[11];
    const float* bout = (const float*)d_in[12];

    float* out  = (float*)d_out;
    float* kout = out  + (long long)NB * SQ * DH;
    float* vout = kout + (long long)NB * KVLEN * DH;

    void* p;
    cudaGetSymbolAddress(&p, g_scores); float* scores = (float*)p;
    cudaGetSymbolAddress(&p, g_xs);     __nv_bfloat16* xs    = (__nv_bfloat16*)p;
    cudaGetSymbolAddress(&p, g_qs);     __nv_bfloat16* qs    = (__nv_bfloat16*)p;
    cudaGetSymbolAddress(&p, g_ks);     __nv_bfloat16* ks    = (__nv_bfloat16*)p;
    cudaGetSymbolAddress(&p, g_vts);    __nv_bfloat16* vts   = (__nv_bfloat16*)p;
    cudaGetSymbolAddress(&p, g_attns);  __nv_bfloat16* attns = (__nv_bfloat16*)p;
    cudaGetSymbolAddress(&p, g_ctxs);   __nv_bfloat16* ctxs  = (__nv_bfloat16*)p;
    cudaGetSymbolAddress(&p, g_ffs);    __nv_bfloat16* ffs   = (__nv_bfloat16*)p;
    cudaGetSymbolAddress(&p, g_wqs);    __nv_bfloat16* wqs   = (__nv_bfloat16*)p;
    cudaGetSymbolAddress(&p, g_wks);    __nv_bfloat16* wks   = (__nv_bfloat16*)p;
    cudaGetSymbolAddress(&p, g_wvs);    __nv_bfloat16* wvs   = (__nv_bfloat16*)p;
    cudaGetSymbolAddress(&p, g_wffs);   __nv_bfloat16* wffs  = (__nv_bfloat16*)p;
    cudaGetSymbolAddress(&p, g_wouts);  __nv_bfloat16* wouts = (__nv_bfloat16*)p;

    dim3 t32x8(32, 8);

    // 0) input splits + weight transpose-splits + past-cache copy
    split_rows<false><<<2048, 256>>>(x, xs, (long long)NB * SQ, DIN);
    transpose_split<<<dim3(DH / 32, DIN / 32, 1), t32x8>>>(Wq, wqs, DIN, DH, 0, 0);
    transpose_split<<<dim3(DH / 32, DIN / 32, 1), t32x8>>>(Wk, wks, DIN, DH, 0, 0);
    transpose_split<<<dim3(DH / 32, DIN / 32, 1), t32x8>>>(Wv, wvs, DIN, DH, 0, 0);
    transpose_split<<<dim3(DFF / 32, DH / 32, 1), t32x8>>>(Wff, wffs, DH, DFF, 0, 0);
    transpose_split<<<dim3(DH / 32, DFF / 32, 1), t32x8>>>(Wout, wouts, DFF, DH, 0, 0);
    cache_copy<<<2048, 256>>>(kc, vc, kout, vout);

    // 1) projections (K' = 3*DIN = 6144)
    gemm_mma<<<dim3(DH / 128, (NB * SQ) / 128, 1), 256>>>(
        xs, wqs, bq, nullptr, qs, DH, 3 * DIN, 0, 0, NB * SQ, 0);
    gemm_mma<<<dim3(DH / 128, SQ / 128, NB), 256>>>(
        xs, wks, bk, kout, nullptr, DH, 3 * DIN, (long long)SQ * 3 * DIN, 0, KVLEN, PAST);
    gemm_mma<<<dim3(DH / 128, SQ / 128, NB), 256>>>(
        xs, wvs, bv, vout, nullptr, DH, 3 * DIN, (long long)SQ * 3 * DIN, 0, KVLEN, PAST);

    // 2) split full K cache (B-order) and transpose-split full V cache
    split_rows<true><<<2048, 256>>>(kout, ks, (long long)NB * KVLEN, DH);
    transpose_split<<<dim3(DH / 32, KVLEN / 32, NB), t32x8>>>(
        vout, vts, KVLEN, DH, (long long)KVLEN * DH, (long long)DH * 3 * KVLEN);

    // 3) scores[b] = q'[b] @ k'[b]^T   (M=2048, N=4096, K'=6144)
    gemm_mma<<<dim3(KVLEN / 128, SQ / 128, NB), 256>>>(
        qs, ks, nullptr, scores, nullptr, KVLEN, 3 * DH,
        (long long)SQ * 3 * DH, (long long)KVLEN * 3 * DH, SQ, 0);

    // 4) softmax over query axis + attn split
    softmax_split<<<dim3(KVLEN / 256, NB), 256>>>(scores, attns);

    // 5) ctx[b] = attn'[b] @ v'^T[b]^T  (M=2048, N=2048, K'=12288)
    gemm_mma<<<dim3(DH / 128, SQ / 128, NB), 256>>>(
        attns, vts, nullptr, nullptr, ctxs, DH, 3 * KVLEN,
        (long long)SQ * 3 * KVLEN, (long long)DH * 3 * KVLEN, SQ, 0);

    // 6) FFN (M=8192): ff = ctx' @ Wff'^T ; out = ff' @ Wout'^T
    gemm_mma<<<dim3(DFF / 128, (NB * SQ) / 128, 1), 256>>>(
        ctxs, wffs, bff, nullptr, ffs, DFF, 3 * DH, 0, 0, NB * SQ, 0);
    gemm_mma<<<dim3(DH / 128, (NB * SQ) / 128, 1), 256>>>(
        ffs, wouts, bout, out, nullptr, DH, 3 * DFF, 0, 0, NB * SQ, 0);
}

// round 6
// speedup vs baseline: 3.1317x; 1.7174x over previous
#include <cuda_runtime.h>
#include <cuda_bf16.h>
#include <cuda_fp16.h>
#include <cstdint>

#define NB    4
#define SQ    2048
#define PAST  2048
#define DIN   2048
#define DH    2048
#define DFF   8192
#define KVLEN (PAST + SQ)   // 4096

// ======================= device scratch (no allocation) ======================
__device__ float g_scores[(long long)NB * SQ * KVLEN];            // 134 MB
__device__ __nv_bfloat16 g_xs [(long long)NB*SQ * 3*DIN];         // 100 MB
__device__ __nv_bfloat16 g_qs [(long long)NB*SQ * 3*DH];          // 100 MB
__device__ __nv_bfloat16 g_ks [(long long)NB*KVLEN * 3*DH];       // 201 MB
__device__ __nv_bfloat16 g_wqs[(long long)DH * 3*DIN];            // 25 MB
__device__ __nv_bfloat16 g_wks[(long long)DH * 3*DIN];            // 25 MB
__device__ __half g_xh   [(long long)NB*SQ * DIN];                // 33.5 MB
__device__ __half g_wvh  [(long long)DH * DIN];                   // 8.4 MB
__device__ __half g_wffh [(long long)DFF * DH];                   // 33.5 MB
__device__ __half g_wouth[(long long)DH * DFF];                   // 33.5 MB
__device__ __half g_vth  [(long long)NB * DH * KVLEN];            // 67 MB
__device__ __half g_attnh[(long long)NB * SQ * KVLEN];            // 67 MB
__device__ __half g_ctxh [(long long)NB * SQ * DH];               // 33.5 MB
__device__ __half g_ffh  [(long long)NB * SQ * DFF];              // 134 MB

// ======================= helpers =============================================
__device__ __forceinline__ uint32_t smem_u32(const void* p) {
    uint32_t a;
    asm("{ .reg .u64 t; cvta.to.shared.u64 t, %1; cvt.u32.u64 %0, t; }" : "=r"(a) : "l"(p));
    return a;
}
__device__ __forceinline__ void ldm4(uint32_t* f, uint32_t a) {
    asm volatile("ldmatrix.sync.aligned.m8n8.x4.shared.b16 {%0,%1,%2,%3}, [%4];"
                 : "=r"(f[0]), "=r"(f[1]), "=r"(f[2]), "=r"(f[3]) : "r"(a));
}
template<int DT>   // 0 = bf16, 1 = f16
__device__ __forceinline__ void mma_op(float* c, const uint32_t* a, uint32_t b0, uint32_t b1) {
    if (DT == 0)
        asm volatile("mma.sync.aligned.m16n8k16.row.col.f32.bf16.bf16.f32 "
                     "{%0,%1,%2,%3}, {%4,%5,%6,%7}, {%8,%9}, {%0,%1,%2,%3};"
                     : "+f"(c[0]), "+f"(c[1]), "+f"(c[2]), "+f"(c[3])
                     : "r"(a[0]), "r"(a[1]), "r"(a[2]), "r"(a[3]), "r"(b0), "r"(b1));
    else
        asm volatile("mma.sync.aligned.m16n8k16.row.col.f32.f16.f16.f32 "
                     "{%0,%1,%2,%3}, {%4,%5,%6,%7}, {%8,%9}, {%0,%1,%2,%3};"
                     : "+f"(c[0]), "+f"(c[1]), "+f"(c[2]), "+f"(c[3])
                     : "r"(a[0]), "r"(a[1]), "r"(a[2]), "r"(a[3]), "r"(b0), "r"(b1));
}
__device__ __forceinline__ unsigned short bf16bits(float f) {
    __nv_bfloat16 h = __float2bfloat16(f);
    return *reinterpret_cast<unsigned short*>(&h);
}
__device__ __forceinline__ float bf16val(unsigned short u) {
    __nv_bfloat16 h = *reinterpret_cast<__nv_bfloat16*>(&u);
    return __bfloat162float(h);
}
__device__ __forceinline__ uint32_t swz(int r, int j) {   // 16B seg j in 64B row r
    return (uint32_t)(r * 64 + ((j ^ ((r >> 1) & 3)) << 4));
}
#define CP16(dst, src) asm volatile("cp.async.ca.shared.global [%0], [%1], 16;" :: "r"(dst), "l"(src) : "memory")
#define CP_COMMIT()    asm volatile("cp.async.commit_group;" ::: "memory")

// ======================= GEMM: C[M,N] = A[M,K]·B[N,K]^T =====================
// Tile 128x128x32, 8 warps (4M x 2N), warp 32x64, 3-stage cp.async pipeline.
// Outputs (all nullable): C fp32; sA3 bf16 3-seg split (hi,hi,lo) stride 3N; sH fp16 stride N.
template<int DT>
__global__ void __launch_bounds__(256, 2)
gemm_tc(const uint16_t* __restrict__ A, const uint16_t* __restrict__ B,
        const float* __restrict__ bias, float* __restrict__ C,
        __nv_bfloat16* __restrict__ sA3, __half* __restrict__ sH,
        int N, long long Kp,
        long long aBatch, long long bBatch,
        int cBatchRows, int cRowOff)
{
    __shared__ __align__(16) uint8_t As[3][8192];
    __shared__ __align__(16) uint8_t Bs[3][8192];

    const int tid = threadIdx.x;
    const int wid = tid >> 5;
    const int lid = tid & 31;
    const long long bn0 = (long long)blockIdx.x * 128;
    const long long bm0 = (long long)blockIdx.y * 128;

    A += (long long)blockIdx.z * aBatch + bm0 * Kp;
    B += (long long)blockIdx.z * bBatch + bn0 * Kp;

    // loader: 2 segs per operand per thread (512 segs = 128 rows x 4x16B)
    const int u0 = tid, u1 = tid + 256;
    const int lr0 = u0 >> 2, lj0 = u0 & 3;
    const int lr1 = u1 >> 2, lj1 = u1 & 3;
    const uint16_t* aG0 = A + (long long)lr0 * Kp + lj0 * 8;
    const uint16_t* aG1 = A + (long long)lr1 * Kp + lj1 * 8;
    const uint16_t* bG0 = B + (long long)lr0 * Kp + lj0 * 8;
    const uint16_t* bG1 = B + (long long)lr1 * Kp + lj1 * 8;
    const uint32_t sa0 = swz(lr0, lj0), sa1 = swz(lr1, lj1);
    const uint32_t aSm = smem_u32(As), bSm = smem_u32(Bs);

    const int nT = (int)(Kp >> 5);

    auto ldStage = [&](int slot, int chunk) {
        const long long o = (long long)chunk * 32;
        const uint32_t ab = aSm + slot * 8192, bb = bSm + slot * 8192;
        CP16(ab + sa0, aG0 + o);
        CP16(ab + sa1, aG1 + o);
        CP16(bb + sa0, bG0 + o);
        CP16(bb + sa1, bG1 + o);
        CP_COMMIT();
    };
    ldStage(0, 0);
    ldStage(1, 1);

    // fragment addressing
    const int wm = wid >> 1, wn = wid & 1;
    const int l15 = lid & 15, h = lid >> 4;
    uint32_t aoff[2]; int ax[2];
#pragma unroll
    for (int i = 0; i < 2; i++) {
        const int r = wm * 32 + i * 16 + l15;
        aoff[i] = r * 64; ax[i] = (r >> 1) & 3;
    }
    uint32_t boff[4]; int bx[4];
#pragma unroll
    for (int g = 0; g < 4; g++) {
        const int r = wn * 64 + g * 16 + l15;
        boff[g] = r * 64; bx[g] = (r >> 1) & 3;
    }

    float acc[2][8][4];
#pragma unroll
    for (int i = 0; i < 2; i++)
#pragma unroll
        for (int j = 0; j < 8; j++)
#pragma unroll
            for (int k = 0; k < 4; k++) acc[i][j][k] = 0.f;

    for (int t = 0; t < nT; t++) {
        if (t + 1 < nT) asm volatile("cp.async.wait_group 1;" ::: "memory");
        else            asm volatile("cp.async.wait_group 0;" ::: "memory");
        __syncthreads();
        if (t + 2 < nT) ldStage((t + 2) % 3, t + 2);

        const int slot = t % 3;
        const uint32_t aB = aSm + slot * 8192;
        const uint32_t bB = bSm + slot * 8192;
#pragma unroll
        for (int s = 0; s < 2; s++) {
            uint32_t af[2][4], bfr[4][4];
            const int jb = 2 * s + h;
#pragma unroll
            for (int i = 0; i < 2; i++)
                ldm4(af[i], aB + aoff[i] + (uint32_t)((jb ^ ax[i]) << 4));
#pragma unroll
            for (int g = 0; g < 4; g++)
                ldm4(bfr[g], bB + boff[g] + (uint32_t)((jb ^ bx[g]) << 4));
#pragma unroll
            for (int mi = 0; mi < 2; mi++)
#pragma unroll
                for (int g = 0; g < 4; g++) {
                    mma_op<DT>(acc[mi][2 * g],     af[mi], bfr[g][0], bfr[g][2]);
                    mma_op<DT>(acc[mi][2 * g + 1], af[mi], bfr[g][1], bfr[g][3]);
                }
        }
    }

    // epilogue
    const long long rowBase = (long long)blockIdx.z * cBatchRows + cRowOff + bm0 + wm * 32;
    const int colW = (int)bn0 + wn * 64;
#pragma unroll
    for (int mi = 0; mi < 2; mi++) {
        const long long r0 = rowBase + mi * 16 + (lid >> 2);
        const long long r1 = r0 + 8;
#pragma unroll
        for (int nj = 0; nj < 8; nj++) {
            const int col = colW + nj * 8 + (lid & 3) * 2;
            float b0 = 0.f, b1 = 0.f;
            if (bias) { b0 = bias[col]; b1 = bias[col + 1]; }
            const float v00 = acc[mi][nj][0] + b0, v01 = acc[mi][nj][1] + b1;
            const float v10 = acc[mi][nj][2] + b0, v11 = acc[mi][nj][3] + b1;
            if (C) {
                *(float2*)&C[r0 * N + col] = make_float2(v00, v01);
                *(float2*)&C[r1 * N + col] = make_float2(v10, v11);
            }
            if (sA3) {
                unsigned short h0 = bf16bits(v00), h1 = bf16bits(v01);
                ushort2 H = { h0, h1 };
                ushort2 L = { bf16bits(v00 - bf16val(h0)), bf16bits(v01 - bf16val(h1)) };
                unsigned short* sr = (unsigned short*)(sA3 + r0 * (3LL * N));
                *(ushort2*)(sr + col) = H;
                *(ushort2*)(sr + N + col) = H;
                *(ushort2*)(sr + 2LL * N + col) = L;
                h0 = bf16bits(v10); h1 = bf16bits(v11);
                H = { h0, h1 };
                L = { bf16bits(v10 - bf16val(h0)), bf16bits(v11 - bf16val(h1)) };
                sr = (unsigned short*)(sA3 + r1 * (3LL * N));
                *(ushort2*)(sr + col) = H;
                *(ushort2*)(sr + N + col) = H;
                *(ushort2*)(sr + 2LL * N + col) = L;
            }
            if (sH) {
                *(__half2*)&sH[r0 * N + col] = __floats2half2_rn(v00, v01);
                *(__half2*)&sH[r1 * N + col] = __floats2half2_rn(v10, v11);
            }
        }
    }
}

// ======================= split / convert / transpose kernels =================
// BSPLIT=false: (hi,hi,lo) [A operand]; true: (hi,lo,hi) [B operand]
template<bool BSPLIT>
__global__ void split_rows(const float* __restrict__ in, __nv_bfloat16* __restrict__ out,
                           long long R, int K)
{
    const long long total = R * (long long)(K >> 2);
    const int K4 = K >> 2;
    for (long long i = (long long)blockIdx.x * blockDim.x + threadIdx.x;
         i < total; i += (long long)gridDim.x * blockDim.x) {
        const long long r = i / K4;
        const int k = (int)(i - r * K4) << 2;
        const float4 v = ((const float4*)in)[i];
        ushort4 H, L;
        H.x = bf16bits(v.x); L.x = bf16bits(v.x - bf16val(H.x));
        H.y = bf16bits(v.y); L.y = bf16bits(v.y - bf16val(H.y));
        H.z = bf16bits(v.z); L.z = bf16bits(v.z - bf16val(H.z));
        H.w = bf16bits(v.w); L.w = bf16bits(v.w - bf16val(H.w));
        unsigned short* row = (unsigned short*)(out + r * (3LL * K));
        *(ushort4*)(row + k) = H;
        if (BSPLIT) { *(ushort4*)(row + K + k) = L; *(ushort4*)(row + 2 * K + k) = H; }
        else        { *(ushort4*)(row + K + k) = H; *(ushort4*)(row + 2 * K + k) = L; }
    }
}

// fp32 [Kd, Nd] -> bf16 [Nd, 3*Kd] segments (hi,lo,hi)
__global__ void transpose_split(const float* __restrict__ in, __nv_bfloat16* __restrict__ out,
                                int Kd, int Nd)
{
    __shared__ float tile[32][33];
    const int k0 = blockIdx.y * 32, n0 = blockIdx.x * 32;
    for (int i = threadIdx.y; i < 32; i += 8)
        tile[i][threadIdx.x] = in[(long long)(k0 + i) * Nd + n0 + threadIdx.x];
    __syncthreads();
    for (int i = threadIdx.y; i < 32; i += 8) {
        const int n = n0 + i, k = k0 + threadIdx.x;
        const float v = tile[threadIdx.x][i];
        const unsigned short hb = bf16bits(v);
        const unsigned short lb = bf16bits(v - bf16val(hb));
        unsigned short* row = (unsigned short*)(out + (long long)n * (3LL * Kd));
        row[k] = hb; row[Kd + k] = lb; row[2 * Kd + k] = hb;
    }
}

// fp32 [Kd, Nd] -> fp16 [Nd, Kd]
__global__ void transpose_h(const float* __restrict__ in, __half* __restrict__ out,
                            int Kd, int Nd, long long inBatch, long long outBatch)
{
    __shared__ float tile[32][33];
    in  += (long long)blockIdx.z * inBatch;
    out += (long long)blockIdx.z * outBatch;
    const int k0 = blockIdx.y * 32, n0 = blockIdx.x * 32;
    for (int i = threadIdx.y; i < 32; i += 8)
        tile[i][threadIdx.x] = in[(long long)(k0 + i) * Nd + n0 + threadIdx.x];
    __syncthreads();
    for (int i = threadIdx.y; i < 32; i += 8) {
        const int n = n0 + i, k = k0 + threadIdx.x;
        out[(long long)n * Kd + k] = __float2half_rn(tile[threadIdx.x][i]);
    }
}

// fp32 -> fp16 elementwise (vectorized)
__global__ void cvt_half(const float* __restrict__ in, __half* __restrict__ out, long long n4)
{
    for (long long i = (long long)blockIdx.x * blockDim.x + threadIdx.x;
         i < n4; i += (long long)gridDim.x * blockDim.x) {
        const float4 v = ((const float4*)in)[i];
        __half2 a = __floats2half2_rn(v.x, v.y);
        __half2 b = __floats2half2_rn(v.z, v.w);
        ((__half2*)out)[2 * i]     = a;
        ((__half2*)out)[2 * i + 1] = b;
    }
}

// ======================= softmax over QUERY axis -> fp16 =====================
__global__ void softmax_h(float* __restrict__ s, __half* __restrict__ attnh)
{
    const int col = blockIdx.x * blockDim.x + threadIdx.x;
    const int b = blockIdx.y;
    float* base = s + (long long)b * SQ * KVLEN + col;
    float mx = -1e30f;
    for (int r = 0; r < SQ; r++) mx = fmaxf(mx, base[(long long)r * KVLEN]);
    float sum = 0.f;
    for (int r = 0; r < SQ; r++) {
        const long long idx = (long long)r * KVLEN;
        const float e = __expf(base[idx] - mx);
        base[idx] = e;
        sum += e;
    }
    const float inv = 1.f / sum;
    __half* a = attnh + (long long)b * SQ * KVLEN + col;
    for (int r = 0; r < SQ; r++)
        a[(long long)r * KVLEN] = __float2half_rn(base[(long long)r * KVLEN] * inv);
}

// ======================= KV cache copy =======================================
__global__ void cache_copy(const float* __restrict__ kc, const float* __restrict__ vc,
                           float* __restrict__ kout, float* __restrict__ vout)
{
    const long long per = (long long)PAST * DH / 4;
    const long long tot = per * NB;
    for (long long i = (long long)blockIdx.x * blockDim.x + threadIdx.x;
         i < tot; i += (long long)gridDim.x * blockDim.x) {
        const int b = (int)(i / per);
        const long long o = i - (long long)b * per;
        const long long dst = (long long)b * ((long long)KVLEN * DH / 4) + o;
        ((float4*)kout)[dst] = ((const float4*)kc)[i];
        ((float4*)vout)[dst] = ((const float4*)vc)[i];
    }
}

// =============================================================================
extern "C" void kernel_launch(void* const* d_in, const int* in_sizes, int n_in,
                              void* d_out, int out_size)
{
    const float* x    = (const float*)d_in[0];
    const float* kc   = (const float*)d_in[1];
    const float* vc   = (const float*)d_in[2];
    const float* Wq   = (const float*)d_in[3];
    const float* bq   = (const float*)d_in[4];
    const float* Wk   = (const float*)d_in[5];
    const float* bk   = (const float*)d_in[6];
    const float* Wv   = (const float*)d_in[7];
    const float* bv   = (const float*)d_in[8];
    const float* Wff  = (const float*)d_in[9];
    const float* bff  = (const float*)d_in[10];
    const float* Wout = (const float*)d_in[11];
    const float* bout = (const float*)d_in[12];

    float* out  = (float*)d_out;
    float* kout = out  + (long long)NB * SQ * DH;
    float* vout = kout + (long long)NB * KVLEN * DH;

    void* p;
    cudaGetSymbolAddress(&p, g_scores); float* scores = (float*)p;
    cudaGetSymbolAddress(&p, g_xs);    __nv_bfloat16* xs  = (__nv_bfloat16*)p;
    cudaGetSymbolAddress(&p, g_qs);    __nv_bfloat16* qs  = (__nv_bfloat16*)p;
    cudaGetSymbolAddress(&p, g_ks);    __nv_bfloat16* ks  = (__nv_bfloat16*)p;
    cudaGetSymbolAddress(&p, g_wqs);   __nv_bfloat16* wqs = (__nv_bfloat16*)p;
    cudaGetSymbolAddress(&p, g_wks);   __nv_bfloat16* wks = (__nv_bfloat16*)p;
    cudaGetSymbolAddress(&p, g_xh);    __half* xh    = (__half*)p;
    cudaGetSymbolAddress(&p, g_wvh);   __half* wvh   = (__half*)p;
    cudaGetSymbolAddress(&p, g_wffh);  __half* wffh  = (__half*)p;
    cudaGetSymbolAddress(&p, g_wouth); __half* wouth = (__half*)p;
    cudaGetSymbolAddress(&p, g_vth);   __half* vth   = (__half*)p;
    cudaGetSymbolAddress(&p, g_attnh); __half* attnh = (__half*)p;
    cudaGetSymbolAddress(&p, g_ctxh);  __half* ctxh  = (__half*)p;
    cudaGetSymbolAddress(&p, g_ffh);   __half* ffh   = (__half*)p;

    dim3 t32x8(32, 8);
    const int M = NB * SQ;  // 8192

    // 0) operand prep
    split_rows<false><<<2048, 256>>>(x, xs, (long long)M, DIN);
    cvt_half<<<2048, 256>>>(x, xh, (long long)M * DIN / 4);
    transpose_split<<<dim3(DH / 32, DIN / 32, 1), t32x8>>>(Wq, wqs, DIN, DH);
    transpose_split<<<dim3(DH / 32, DIN / 32, 1), t32x8>>>(Wk, wks, DIN, DH);
    transpose_h<<<dim3(DH / 32, DIN / 32, 1), t32x8>>>(Wv, wvh, DIN, DH, 0, 0);
    transpose_h<<<dim3(DFF / 32, DH / 32, 1), t32x8>>>(Wff, wffh, DH, DFF, 0, 0);
    transpose_h<<<dim3(DH / 32, DFF / 32, 1), t32x8>>>(Wout, wouth, DFF, DH, 0, 0);
    cache_copy<<<2048, 256>>>(kc, vc, kout, vout);

    // 1) projections: q,k bf16x3 (K'=6144); v plain fp16 (K=2048)
    gemm_tc<0><<<dim3(DH / 128, M / 128, 1), 256>>>(
        (const uint16_t*)xs, (const uint16_t*)wqs, bq, nullptr, qs, nullptr,
        DH, 3 * DIN, 0, 0, M, 0);
    gemm_tc<0><<<dim3(DH / 128, SQ / 128, NB), 256>>>(
        (const uint16_t*)xs, (const uint16_t*)wks, bk, kout, nullptr, nullptr,
        DH, 3 * DIN, (long long)SQ * 3 * DIN, 0, KVLEN, PAST);
    gemm_tc<1><<<dim3(DH / 128, SQ / 128, NB), 256>>>(
        (const uint16_t*)xh, (const uint16_t*)wvh, bv, vout, nullptr, nullptr,
        DH, DIN, (long long)SQ * DIN, 0, KVLEN, PAST);

    // 2) K cache -> bf16 B-split; V cache -> fp16 transpose
    split_rows<true><<<2048, 256>>>(kout, ks, (long long)NB * KVLEN, DH);
    transpose_h<<<dim3(DH / 32, KVLEN / 32, NB), t32x8>>>(
        vout, vth, KVLEN, DH, (long long)KVLEN * DH, (long long)DH * KVLEN);

    // 3) scores = q' @ k'^T  (bf16x3, K'=6144)
    gemm_tc<0><<<dim3(KVLEN / 128, SQ / 128, NB), 256>>>(
        (const uint16_t*)qs, (const uint16_t*)ks, nullptr, scores, nullptr, nullptr,
        KVLEN, 3 * DH, (long long)SQ * 3 * DH, (long long)KVLEN * 3 * DH, SQ, 0);

    // 4) softmax over query axis -> fp16 attn
    softmax_h<<<dim3(KVLEN / 256, NB), 256>>>(scores, attnh);

    // 5) ctx = attn @ v  (fp16, K=4096) -> fp16 ctx
    gemm_tc<1><<<dim3(DH / 128, SQ / 128, NB), 256>>>(
        (const uint16_t*)attnh, (const uint16_t*)vth, nullptr, nullptr, nullptr, ctxh,
        DH, KVLEN, (long long)SQ * KVLEN, (long long)DH * KVLEN, SQ, 0);

    // 6) FFN (fp16): ff = ctx @ Wff^T + bff ; out = ff @ Wout^T + bout
    gemm_tc<1><<<dim3(DFF / 128, M / 128, 1), 256>>>(
        (const uint16_t*)ctxh, (const uint16_t*)wffh, bff, nullptr, nullptr, ffh,
        DFF, DH, 0, 0, M, 0);
    gemm_tc<1><<<dim3(DH / 128, M / 128, 1), 256>>>(
        (const uint16_t*)ffh, (const uint16_t*)wouth, bout, out, nullptr, nullptr,
        DH, DFF, 0, 0, M, 0);
}